// round 9
// baseline (speedup 1.0000x reference)
#include <cuda_runtime.h>
#include <cuda_bf16.h>
#include <math.h>
#include <cstdint>

#define B_    2
#define S_    2048
#define HID   2048
#define HQ    16
#define HKV   4
#define D_    128
#define MROWS (B_ * S_)      // 4096
#define KVW   (HKV * D_)     // 512

// ---------------- scratch (allocation-free: __device__ globals) ----------------
__device__ float g_gate[(size_t)MROWS * HID];

// q/k/v in bf16 hi/lo, [b][h][s][d]
__device__ __nv_bfloat16 g_qh[(size_t)B_ * HQ  * S_ * D_];
__device__ __nv_bfloat16 g_ql[(size_t)B_ * HQ  * S_ * D_];
__device__ __nv_bfloat16 g_kh[(size_t)B_ * HKV * S_ * D_];
__device__ __nv_bfloat16 g_kl[(size_t)B_ * HKV * S_ * D_];
__device__ __nv_bfloat16 g_vh[(size_t)B_ * HKV * S_ * D_];
__device__ __nv_bfloat16 g_vl[(size_t)B_ * HKV * S_ * D_];

// bf16 hi/lo splits for GEMMs
__device__ __nv_bfloat16 g_hs_hi[(size_t)MROWS * HID];
__device__ __nv_bfloat16 g_hs_lo[(size_t)MROWS * HID];
__device__ __nv_bfloat16 g_wq_hi[(size_t)HID * HID];
__device__ __nv_bfloat16 g_wq_lo[(size_t)HID * HID];
__device__ __nv_bfloat16 g_wk_hi[(size_t)KVW * HID];
__device__ __nv_bfloat16 g_wk_lo[(size_t)KVW * HID];
__device__ __nv_bfloat16 g_wv_hi[(size_t)KVW * HID];
__device__ __nv_bfloat16 g_wv_lo[(size_t)KVW * HID];
__device__ __nv_bfloat16 g_wg_hi[(size_t)HID * HID];
__device__ __nv_bfloat16 g_wg_lo[(size_t)HID * HID];
__device__ __nv_bfloat16 g_wo_hi[(size_t)HID * HID];
__device__ __nv_bfloat16 g_wo_lo[(size_t)HID * HID];
__device__ __nv_bfloat16 g_at_hi[(size_t)MROWS * HID];
__device__ __nv_bfloat16 g_at_lo[(size_t)MROWS * HID];

// ---------------- PTX helpers (base sm_100-safe) ----------------
__device__ __forceinline__ uint32_t smem_u32(const void* p) {
    return (uint32_t)__cvta_generic_to_shared(p);
}
#define CP16(dst, src) \
    asm volatile("cp.async.cg.shared.global [%0], [%1], 16;\n" :: "r"(dst), "l"(src))
#define CP_COMMIT() asm volatile("cp.async.commit_group;\n" ::: "memory")
#define CP_WAIT(n)  asm volatile("cp.async.wait_group %0;\n" :: "n"(n) : "memory")

#define LDMX4(r, addr) \
    asm volatile("ldmatrix.sync.aligned.m8n8.x4.shared.b16 {%0,%1,%2,%3}, [%4];" \
        : "=r"((r)[0]), "=r"((r)[1]), "=r"((r)[2]), "=r"((r)[3]) : "r"(addr))
#define LDMX4T(r, addr) \
    asm volatile("ldmatrix.sync.aligned.m8n8.x4.trans.shared.b16 {%0,%1,%2,%3}, [%4];" \
        : "=r"((r)[0]), "=r"((r)[1]), "=r"((r)[2]), "=r"((r)[3]) : "r"(addr))

#define MMA16816(d, a, b) \
    asm volatile("mma.sync.aligned.m16n8k16.row.col.f32.bf16.bf16.f32 " \
        "{%0,%1,%2,%3}, {%4,%5,%6,%7}, {%8,%9}, {%0,%1,%2,%3};" \
        : "+f"((d)[0]), "+f"((d)[1]), "+f"((d)[2]), "+f"((d)[3]) \
        : "r"((a)[0]), "r"((a)[1]), "r"((a)[2]), "r"((a)[3]), "r"((b)[0]), "r"((b)[1]))

__device__ __forceinline__ float fexp2(float x) {
    float y; asm("ex2.approx.ftz.f32 %0, %1;" : "=f"(y) : "f"(x)); return y;
}

// pack 8 fp32 -> bf16 hi/lo (x = hi + lo), 16B vector stores
__device__ __forceinline__ void store_split8(__nv_bfloat16* ph, __nv_bfloat16* pl,
                                             const float* v) {
    __nv_bfloat162 h[4], l[4];
#pragma unroll
    for (int i = 0; i < 4; ++i) {
        __nv_bfloat16 a = __float2bfloat16(v[2 * i]);
        __nv_bfloat16 b = __float2bfloat16(v[2 * i + 1]);
        h[i] = __nv_bfloat162(a, b);
        l[i] = __nv_bfloat162(__float2bfloat16(v[2 * i]     - __bfloat162float(a)),
                              __float2bfloat16(v[2 * i + 1] - __bfloat162float(b)));
    }
    *(uint4*)ph = *(const uint4*)h;
    *(uint4*)pl = *(const uint4*)l;
}

// ---------------- split: fp32 -> (bf16 hi, bf16 lo) ----------------
__global__ void __launch_bounds__(256) split_bf16(const float* __restrict__ x,
                                                  __nv_bfloat16* __restrict__ hi,
                                                  __nv_bfloat16* __restrict__ lo, int n)
{
    int i = (blockIdx.x * blockDim.x + threadIdx.x) * 4;
    if (i >= n) return;
    float4 v = *(const float4*)(x + i);
    float vv[4] = {v.x, v.y, v.z, v.w};
    __nv_bfloat162 h[2], l[2];
#pragma unroll
    for (int j = 0; j < 2; ++j) {
        __nv_bfloat16 a = __float2bfloat16(vv[2 * j]);
        __nv_bfloat16 b = __float2bfloat16(vv[2 * j + 1]);
        h[j] = __nv_bfloat162(a, b);
        l[j] = __nv_bfloat162(__float2bfloat16(vv[2 * j]     - __bfloat162float(a)),
                              __float2bfloat16(vv[2 * j + 1] - __bfloat162float(b)));
    }
    *(uint2*)(hi + i) = *(const uint2*)h;
    *(uint2*)(lo + i) = *(const uint2*)l;
}

// ---------------- mma.sync bf16x3 GEMM mainloop: warp tile 64x64, CTA 128x128 ----------------
// 128 threads (4 warps, 2Mx2N), BK=32, rows padded to 80B, cp.async double buffer, 2 CTAs/SM.
#define BK     32
#define ROWB   80
#define OPB    (128 * ROWB)         // 10240
#define STG    (4 * OPB)            // 40960 (Ahi, Alo, Bhi, Blo)
#define GEMM_SMEM (2 * STG)         // 81920

__device__ __forceinline__ void gemm_mainloop(
    const __nv_bfloat16* __restrict__ Ahi, const __nv_bfloat16* __restrict__ Alo,
    const __nv_bfloat16* __restrict__ Bhi, const __nv_bfloat16* __restrict__ Blo,
    int K, int bm, int bn, uint32_t sb, float (&acc)[4][8][4])
{
    const int tid  = threadIdx.x;
    const int wid  = tid >> 5, lane = tid & 31;
    const int wm   = wid & 1;          // 2 warps in M: 64 rows each
    const int wn   = wid >> 1;         // 2 warps in N: 64 cols each

    const uint32_t a_off = (uint32_t)((lane & 15) * ROWB + (lane >> 4) * 16);
    const uint32_t b_off = (uint32_t)((lane & 7) * ROWB + ((lane >> 4) & 1) * (8 * ROWB)
                                      + ((lane >> 3) & 1) * 16);

#pragma unroll
    for (int i = 0; i < 4; ++i)
#pragma unroll
        for (int j = 0; j < 8; ++j)
#pragma unroll
            for (int v = 0; v < 4; ++v) acc[i][j][v] = 0.f;

    const int T = K / BK;

#define FILL(s, kt) do {                                                          \
        uint32_t base = sb + (uint32_t)(s) * STG;                                 \
        int k0 = (kt) * BK;                                                       \
        _Pragma("unroll")                                                         \
        for (int c = 0; c < 4; ++c) {                                             \
            int chunk = c * 128 + tid;                                            \
            int r = chunk >> 2, o16 = (chunk & 3) * 16;                           \
            uint32_t so = (uint32_t)(r * ROWB + o16);                             \
            const char* pah = (const char*)(Ahi + (size_t)(bm + r) * K + k0) + o16; \
            const char* pal = (const char*)(Alo + (size_t)(bm + r) * K + k0) + o16; \
            const char* pbh = (const char*)(Bhi + (size_t)(bn + r) * K + k0) + o16; \
            const char* pbl = (const char*)(Blo + (size_t)(bn + r) * K + k0) + o16; \
            CP16(base + so,           pah);                                       \
            CP16(base + OPB + so,     pal);                                       \
            CP16(base + 2 * OPB + so, pbh);                                       \
            CP16(base + 3 * OPB + so, pbl);                                       \
        }                                                                         \
    } while (0)

    FILL(0, 0); CP_COMMIT();

    for (int t = 0; t < T; ++t) {
        const int s = t & 1;
        if (t + 1 < T) { FILL(s ^ 1, t + 1); CP_COMMIT(); CP_WAIT(1); }
        else           { CP_WAIT(0); }
        __syncthreads();

        const uint32_t abase = sb + (uint32_t)s * STG + (uint32_t)(wm * 64) * ROWB;
        const uint32_t bbase = sb + (uint32_t)s * STG + 2 * OPB + (uint32_t)(wn * 64) * ROWB;

#pragma unroll
        for (int ks = 0; ks < 2; ++ks) {
            uint32_t ah[4][4], al[4][4];
#pragma unroll
            for (int mi = 0; mi < 4; ++mi) {
                uint32_t aa = abase + (uint32_t)(mi * 16) * ROWB + a_off + ks * 32;
                LDMX4(ah[mi], aa);
                LDMX4(al[mi], aa + OPB);
            }
#pragma unroll
            for (int p = 0; p < 4; ++p) {
                uint32_t bh[4], bl[4];
                uint32_t ba = bbase + (uint32_t)(p * 16) * ROWB + b_off + ks * 32;
                LDMX4(bh, ba);
                LDMX4(bl, ba + OPB);
#pragma unroll
                for (int mi = 0; mi < 4; ++mi) {
                    MMA16816(acc[mi][2 * p],     ah[mi], bh);
                    MMA16816(acc[mi][2 * p + 1], ah[mi], bh + 2);
                    MMA16816(acc[mi][2 * p],     ah[mi], bl);
                    MMA16816(acc[mi][2 * p + 1], ah[mi], bl + 2);
                    MMA16816(acc[mi][2 * p],     al[mi], bh);
                    MMA16816(acc[mi][2 * p + 1], al[mi], bh + 2);
                }
            }
        }
        __syncthreads();
    }
#undef FILL
}

// fused Q/K/V/G projections with fused RMSNorm+RoPE+bf16-split epilogue.
// grid.x = 16(Q)+4(K)+4(V)+16(G) = 40, grid.y = 32. One N-tile = one head for Q/K/V.
#define PSTRIDE 132   // fp32 smem tile stride (128x132 floats = 67584 B <= GEMM_SMEM)

__global__ void __launch_bounds__(128, 2) gemm_qkvg(const float* __restrict__ cosT,
                                                    const float* __restrict__ sinT,
                                                    const float* __restrict__ qw,
                                                    const float* __restrict__ kw)
{
    extern __shared__ char smem[];
    const uint32_t sb = smem_u32(smem);
    const int tid = threadIdx.x;
    const int wid = tid >> 5, lane = tid & 31;
    const int wm = wid & 1, wn = wid >> 1;
    const int bx = blockIdx.x;
    const int bm = blockIdx.y * 128;

    const __nv_bfloat16 *Bh, *Bl;
    int bn, mode, head;   // mode: 0=Q, 1=K, 2=V, 3=gate
    if (bx < 16)      { Bh = g_wq_hi; Bl = g_wq_lo; bn = bx * 128;        mode = 0; head = bx; }
    else if (bx < 20) { Bh = g_wk_hi; Bl = g_wk_lo; bn = (bx - 16) * 128; mode = 1; head = bx - 16; }
    else if (bx < 24) { Bh = g_wv_hi; Bl = g_wv_lo; bn = (bx - 20) * 128; mode = 2; head = bx - 20; }
    else              { Bh = g_wg_hi; Bl = g_wg_lo; bn = (bx - 24) * 128; mode = 3; head = 0; }

    float acc[4][8][4];
    gemm_mainloop(g_hs_hi, g_hs_lo, Bh, Bl, HID, bm, bn, sb, acc);

    if (mode == 3) {
        // gate: plain fp32 store
        const int r0 = bm + wm * 64 + (lane >> 2);
        const int c0 = bn + wn * 64 + (lane & 3) * 2;
#pragma unroll
        for (int mi = 0; mi < 4; ++mi)
#pragma unroll
            for (int ni = 0; ni < 8; ++ni) {
                int row = r0 + mi * 16;
                int col = c0 + ni * 8;
                *(float2*)(g_gate + (size_t)row * HID + col) =
                    make_float2(acc[mi][ni][0], acc[mi][ni][1]);
                *(float2*)(g_gate + (size_t)(row + 8) * HID + col) =
                    make_float2(acc[mi][ni][2], acc[mi][ni][3]);
            }
        return;
    }

    // stage the 128x128 fp32 tile in smem (reuses the cp.async stage buffers)
    float* P = (float*)smem;
    {
        const int r0 = wm * 64 + (lane >> 2);
        const int c0 = wn * 64 + (lane & 3) * 2;
#pragma unroll
        for (int mi = 0; mi < 4; ++mi)
#pragma unroll
            for (int ni = 0; ni < 8; ++ni) {
                int r = r0 + mi * 16, c = c0 + ni * 8;
                *(float2*)(P + r * PSTRIDE + c)       = make_float2(acc[mi][ni][0], acc[mi][ni][1]);
                *(float2*)(P + (r + 8) * PSTRIDE + c) = make_float2(acc[mi][ni][2], acc[mi][ni][3]);
            }
    }
    __syncthreads();

    // one thread = one row (full head vector)
    const int m = bm + tid;
    const int b = m >> 11, s = m & (S_ - 1);
    const float* row = P + tid * PSTRIDE;

    if (mode == 2) {
        // V: split only, transposed layout [b][h][s][d]
        size_t obase = ((size_t)(b * HKV + head) * S_ + s) * D_;
        __nv_bfloat16* oh = g_vh + obase;
        __nv_bfloat16* ol = g_vl + obase;
#pragma unroll
        for (int d8 = 0; d8 < 16; ++d8) {
            int d = d8 * 8;
            float v[8];
            *(float4*)&v[0] = *(const float4*)(row + d);
            *(float4*)&v[4] = *(const float4*)(row + d + 4);
            store_split8(oh + d, ol + d, v);
        }
        return;
    }

    // Q/K: RMSNorm + RoPE + split
    float ssum = 0.f;
#pragma unroll
    for (int d = 0; d < D_; d += 4) {
        float4 v = *(const float4*)(row + d);
        ssum += v.x * v.x + v.y * v.y + v.z * v.z + v.w * v.w;
    }
    const float rr = rsqrtf(ssum * (1.f / 128.f) + 1e-6f);
    const float* w = (mode == 0) ? qw : kw;
    size_t obase = (mode == 0) ? ((size_t)(b * HQ  + head) * S_ + s) * D_
                               : ((size_t)(b * HKV + head) * S_ + s) * D_;
    __nv_bfloat16* oh = (mode == 0 ? g_qh : g_kh) + obase;
    __nv_bfloat16* ol = (mode == 0 ? g_ql : g_kl) + obase;
    const float* crow = cosT + (size_t)s * D_;
    const float* srow = sinT + (size_t)s * D_;

#pragma unroll
    for (int d8 = 0; d8 < 8; ++d8) {
        int d = d8 * 8;
        float x[8], y[8], olo[8], ohi[8];
        *(float4*)&x[0] = *(const float4*)(row + d);
        *(float4*)&x[4] = *(const float4*)(row + d + 4);
        *(float4*)&y[0] = *(const float4*)(row + d + 64);
        *(float4*)&y[4] = *(const float4*)(row + d + 68);
#pragma unroll
        for (int i = 0; i < 8; ++i) {
            float xn = x[i] * rr * w[d + i];
            float yn = y[i] * rr * w[d + 64 + i];
            olo[i] = xn * crow[d + i]      - yn * srow[d + i];       // output at dim d+i  (<64)
            ohi[i] = yn * crow[d + 64 + i] + xn * srow[d + 64 + i];  // output at dim d+64+i
        }
        store_split8(oh + d,      ol + d,      olo);
        store_split8(oh + d + 64, ol + d + 64, ohi);
    }
}

// generic GEMM (Wo projection), fp32 epilogue
__global__ void __launch_bounds__(128, 2)
gemm_bf16x3(const __nv_bfloat16* __restrict__ Ahi, const __nv_bfloat16* __restrict__ Alo,
            const __nv_bfloat16* __restrict__ Bhi, const __nv_bfloat16* __restrict__ Blo,
            float* __restrict__ C, int N, int K)
{
    extern __shared__ char smem[];
    const uint32_t sb = smem_u32(smem);
    const int wid = threadIdx.x >> 5, lane = threadIdx.x & 31;
    const int wm = wid & 1, wn = wid >> 1;
    const int bm = blockIdx.y * 128, bn = blockIdx.x * 128;

    float acc[4][8][4];
    gemm_mainloop(Ahi, Alo, Bhi, Blo, K, bm, bn, sb, acc);

    const int r0 = bm + wm * 64 + (lane >> 2);
    const int c0 = bn + wn * 64 + (lane & 3) * 2;
#pragma unroll
    for (int mi = 0; mi < 4; ++mi)
#pragma unroll
        for (int ni = 0; ni < 8; ++ni) {
            int row = r0 + mi * 16;
            int col = c0 + ni * 8;
            *(float2*)(C + (size_t)row * N + col)       = make_float2(acc[mi][ni][0], acc[mi][ni][1]);
            *(float2*)(C + (size_t)(row + 8) * N + col) = make_float2(acc[mi][ni][2], acc[mi][ni][3]);
        }
}

// ---------------- tensor-core flash attention (causal, bf16x3) ----------------
#define QR    128
#define KT    64
#define DSTR  272
#define QARR  (QR * DSTR)
#define KARR  (KT * DSTR)
#define KVSTG (4 * KARR)
#define ATTN_SMEM (2 * QARR + 2 * KVSTG)   // 208896

__global__ void __launch_bounds__(256) attn_tc(const float* __restrict__ gate)
{
    extern __shared__ char smc[];
    const uint32_t sb = smem_u32(smc);
    const int tid = threadIdx.x;
    const int wid = tid >> 5, lane = tid & 31;
    const int bh = blockIdx.y;
    const int b = bh >> 4, h = bh & 15;
    const int kvh = h >> 2;
    const int qt = gridDim.x - 1 - blockIdx.x;
    const int q0 = qt * QR;

    const char* Qh_g = (const char*)(g_qh + ((size_t)(b * HQ + h) * S_ + q0) * D_);
    const char* Ql_g = (const char*)(g_ql + ((size_t)(b * HQ + h) * S_ + q0) * D_);
    const char* Kh_g = (const char*)(g_kh + (size_t)(b * HKV + kvh) * S_ * D_);
    const char* Kl_g = (const char*)(g_kl + (size_t)(b * HKV + kvh) * S_ * D_);
    const char* Vh_g = (const char*)(g_vh + (size_t)(b * HKV + kvh) * S_ * D_);
    const char* Vl_g = (const char*)(g_vl + (size_t)(b * HKV + kvh) * S_ * D_);

    const int T = q0 / KT + 2;

#define KVFILL(s, t) do {                                                   \
        uint32_t base = sb + 2 * QARR + (uint32_t)(s) * KVSTG;              \
        size_t gk = (size_t)(t) * KT * 256;                                 \
        _Pragma("unroll")                                                   \
        for (int c = 0; c < 4; ++c) {                                       \
            int idx = c * 256 + tid;                                        \
            int r = idx >> 4, o16 = (idx & 15) * 16;                        \
            uint32_t so = (uint32_t)(r * DSTR + o16);                       \
            size_t gb = gk + (size_t)r * 256 + o16;                         \
            CP16(base + so,            Kh_g + gb);                          \
            CP16(base + KARR + so,     Kl_g + gb);                          \
            CP16(base + 2 * KARR + so, Vh_g + gb);                          \
            CP16(base + 3 * KARR + so, Vl_g + gb);                          \
        }                                                                   \
    } while (0)

    {
#pragma unroll
        for (int c = 0; c < 8; ++c) {
            int idx = c * 256 + tid;
            int r = idx >> 4, o16 = (idx & 15) * 16;
            uint32_t so = (uint32_t)(r * DSTR + o16);
            size_t gb = (size_t)r * 256 + o16;
            CP16(sb + so,        Qh_g + gb);
            CP16(sb + QARR + so, Ql_g + gb);
        }
        KVFILL(0, 0); CP_COMMIT();
        KVFILL(1, 1); CP_COMMIT();
    }

    const uint32_t a_off = (uint32_t)((lane & 15) * DSTR + (lane >> 4) * 16);
    const uint32_t b_off = (uint32_t)((lane & 7) * DSTR + ((lane >> 4) & 1) * (8 * DSTR)
                                      + ((lane >> 3) & 1) * 16);
    const uint32_t qbase = sb + (uint32_t)(wid * 16) * DSTR;

    float o[16][4];
#pragma unroll
    for (int j = 0; j < 16; ++j)
#pragma unroll
        for (int v = 0; v < 4; ++v) o[j][v] = 0.f;
    float mi[2] = {-1e30f, -1e30f};
    float li[2] = {0.f, 0.f};

    const float SC = 0.08838834764831845f * 1.4426950408889634f;

    for (int t = 0; t < T; ++t) {
        const int s = t & 1;
        if (t + 1 < T) CP_WAIT(1); else CP_WAIT(0);
        __syncthreads();

        const uint32_t kbase = sb + 2 * QARR + (uint32_t)s * KVSTG;
        const uint32_t vbase = kbase + 2 * KARR;

        float sc[8][4];
#pragma unroll
        for (int j = 0; j < 8; ++j)
#pragma unroll
            for (int v = 0; v < 4; ++v) sc[j][v] = 0.f;

#pragma unroll
        for (int kk = 0; kk < 8; ++kk) {
            uint32_t ah[4], al[4];
            uint32_t aa = qbase + a_off + kk * 32;
            LDMX4(ah, aa);
            LDMX4(al, aa + QARR);
#pragma unroll
            for (int p = 0; p < 4; ++p) {
                uint32_t kh[4], kl[4];
                uint32_t ba = kbase + (uint32_t)(p * 16) * DSTR + b_off + kk * 32;
                LDMX4(kh, ba);
                LDMX4(kl, ba + KARR);
                MMA16816(sc[2 * p],     ah, kh);
                MMA16816(sc[2 * p + 1], ah, kh + 2);
                MMA16816(sc[2 * p],     ah, kl);
                MMA16816(sc[2 * p + 1], ah, kl + 2);
                MMA16816(sc[2 * p],     al, kh);
                MMA16816(sc[2 * p + 1], al, kh + 2);
            }
        }

        const int k0 = t * KT;
        const bool tail = (t + 2 >= T);
#pragma unroll
        for (int tl = 0; tl < 8; ++tl)
#pragma unroll
            for (int v = 0; v < 4; ++v) {
                float x = sc[tl][v] * SC;
                if (tail) {
                    int col = k0 + tl * 8 + (lane & 3) * 2 + (v & 1);
                    int row = q0 + wid * 16 + (lane >> 2) + ((v >> 1) << 3);
                    if (col > row) x = -1e30f;
                }
                sc[tl][v] = x;
            }

        uint32_t PH0[8], PH1[8], PL0[8], PL1[8];
#pragma unroll
        for (int hh = 0; hh < 2; ++hh) {
            float rm = -1e30f;
#pragma unroll
            for (int tl = 0; tl < 8; ++tl)
                rm = fmaxf(rm, fmaxf(sc[tl][2 * hh], sc[tl][2 * hh + 1]));
            rm = fmaxf(rm, __shfl_xor_sync(0xffffffffu, rm, 1));
            rm = fmaxf(rm, __shfl_xor_sync(0xffffffffu, rm, 2));
            float mnew = fmaxf(mi[hh], rm);
            float corr = fexp2(mi[hh] - mnew);
            float rs = 0.f;
#pragma unroll
            for (int tl = 0; tl < 8; ++tl) {
                float p0 = fexp2(sc[tl][2 * hh]     - mnew);
                float p1 = fexp2(sc[tl][2 * hh + 1] - mnew);
                rs += p0 + p1;
                __nv_bfloat16 b0 = __float2bfloat16(p0), b1 = __float2bfloat16(p1);
                __nv_bfloat162 hp(b0, b1);
                float l0 = p0 - __bfloat162float(b0);
                float l1 = p1 - __bfloat162float(b1);
                __nv_bfloat162 lp(__float2bfloat16(l0), __float2bfloat16(l1));
                if (hh == 0) { PH0[tl] = *(uint32_t*)&hp; PL0[tl] = *(uint32_t*)&lp; }
                else         { PH1[tl] = *(uint32_t*)&hp; PL1[tl] = *(uint32_t*)&lp; }
            }
            rs += __shfl_xor_sync(0xffffffffu, rs, 1);
            rs += __shfl_xor_sync(0xffffffffu, rs, 2);
            li[hh] = li[hh] * corr + rs;
            mi[hh] = mnew;
#pragma unroll
            for (int j = 0; j < 16; ++j) {
                o[j][2 * hh]     *= corr;
                o[j][2 * hh + 1] *= corr;
            }
        }

#pragma unroll
        for (int kk2 = 0; kk2 < 4; ++kk2) {
            uint32_t ph[4] = {PH0[2 * kk2], PH1[2 * kk2], PH0[2 * kk2 + 1], PH1[2 * kk2 + 1]};
            uint32_t pl[4] = {PL0[2 * kk2], PL1[2 * kk2], PL0[2 * kk2 + 1], PL1[2 * kk2 + 1]};
#pragma unroll
            for (int p = 0; p < 8; ++p) {
                uint32_t vh[4], vl[4];
                uint32_t va = vbase + (uint32_t)(kk2 * 16) * DSTR + a_off + p * 32;
                LDMX4T(vh, va);
                LDMX4T(vl, va + KARR);
                MMA16816(o[2 * p],     ph, vh);
                MMA16816(o[2 * p + 1], ph, vh + 2);
                MMA16816(o[2 * p],     ph, vl);
                MMA16816(o[2 * p + 1], ph, vl + 2);
                MMA16816(o[2 * p],     pl, vh);
                MMA16816(o[2 * p + 1], pl, vh + 2);
            }
        }

        __syncthreads();
        if (t + 2 < T) { KVFILL(s, t + 2); CP_COMMIT(); }
    }

#pragma unroll
    for (int hh = 0; hh < 2; ++hh) {
        int row = q0 + wid * 16 + (lane >> 2) + hh * 8;
        size_t m = (size_t)b * S_ + row;
        float inv = 1.f / li[hh];
        const float* gr = gate + m * HID + h * D_;
        __nv_bfloat16* oh = g_at_hi + m * HID + h * D_;
        __nv_bfloat16* ol = g_at_lo + m * HID + h * D_;
#pragma unroll
        for (int j = 0; j < 16; ++j) {
            int d0 = j * 8 + (lane & 3) * 2;
            float2 gv = *(const float2*)(gr + d0);
            float s0 = 1.f / (1.f + fexp2(-gv.x * 1.4426950408889634f));
            float s1 = 1.f / (1.f + fexp2(-gv.y * 1.4426950408889634f));
            float v0 = o[j][2 * hh]     * inv * s0;
            float v1 = o[j][2 * hh + 1] * inv * s1;
            __nv_bfloat16 h0 = __float2bfloat16(v0), h1 = __float2bfloat16(v1);
            __nv_bfloat162 hp(h0, h1);
            __nv_bfloat162 lp(__float2bfloat16(v0 - __bfloat162float(h0)),
                              __float2bfloat16(v1 - __bfloat162float(h1)));
            *(__nv_bfloat162*)(oh + d0) = hp;
            *(__nv_bfloat162*)(ol + d0) = lp;
        }
    }
#undef KVFILL
}

// ---------------- launch ----------------
extern "C" void kernel_launch(void* const* d_in, const int* in_sizes, int n_in,
                              void* d_out, int out_size)
{
    const float* hs   = (const float*)d_in[0];
    const float* cosT = (const float*)d_in[1];
    const float* sinT = (const float*)d_in[2];
    const float* Wq   = (const float*)d_in[3];
    const float* Wk   = (const float*)d_in[4];
    const float* Wv   = (const float*)d_in[5];
    const float* Wg   = (const float*)d_in[6];
    const float* Wo   = (const float*)d_in[7];
    const float* qw   = (const float*)d_in[8];
    const float* kw   = (const float*)d_in[9];
    float* out = (float*)d_out;

    float* gp;
    cudaGetSymbolAddress((void**)&gp, g_gate);

    __nv_bfloat16 *hsh, *hsl, *wqh, *wql, *wkh, *wkl, *wvh, *wvl, *wgh, *wgl, *woh, *wol, *ath, *atl;
    cudaGetSymbolAddress((void**)&hsh, g_hs_hi); cudaGetSymbolAddress((void**)&hsl, g_hs_lo);
    cudaGetSymbolAddress((void**)&wqh, g_wq_hi); cudaGetSymbolAddress((void**)&wql, g_wq_lo);
    cudaGetSymbolAddress((void**)&wkh, g_wk_hi); cudaGetSymbolAddress((void**)&wkl, g_wk_lo);
    cudaGetSymbolAddress((void**)&wvh, g_wv_hi); cudaGetSymbolAddress((void**)&wvl, g_wv_lo);
    cudaGetSymbolAddress((void**)&wgh, g_wg_hi); cudaGetSymbolAddress((void**)&wgl, g_wg_lo);
    cudaGetSymbolAddress((void**)&woh, g_wo_hi); cudaGetSymbolAddress((void**)&wol, g_wo_lo);
    cudaGetSymbolAddress((void**)&ath, g_at_hi); cudaGetSymbolAddress((void**)&atl, g_at_lo);

    cudaFuncSetAttribute(gemm_qkvg,   cudaFuncAttributeMaxDynamicSharedMemorySize, GEMM_SMEM);
    cudaFuncSetAttribute(gemm_bf16x3, cudaFuncAttributeMaxDynamicSharedMemorySize, GEMM_SMEM);
    cudaFuncSetAttribute(attn_tc,     cudaFuncAttributeMaxDynamicSharedMemorySize, ATTN_SMEM);

    // fp32 -> bf16 hi/lo splits
    const int nHS = MROWS * HID, nSq = HID * HID, nKv = KVW * HID;
    split_bf16<<<nHS / 1024, 256>>>(hs, hsh, hsl, nHS);
    split_bf16<<<nSq / 1024, 256>>>(Wq, wqh, wql, nSq);
    split_bf16<<<nKv / 1024, 256>>>(Wk, wkh, wkl, nKv);
    split_bf16<<<nKv / 1024, 256>>>(Wv, wvh, wvl, nKv);
    split_bf16<<<nSq / 1024, 256>>>(Wg, wgh, wgl, nSq);
    split_bf16<<<nSq / 1024, 256>>>(Wo, woh, wol, nSq);

    // fused Q/K/V/G projections + RMSNorm/RoPE/split epilogue (tensor cores, bf16x3)
    gemm_qkvg<<<dim3(40, MROWS / 128), 128, GEMM_SMEM>>>(cosT, sinT, qw, kw);

    // tensor-core causal flash attention + gated epilogue
    attn_tc<<<dim3(S_ / QR, B_ * HQ), 256, ATTN_SMEM>>>(gp);

    // output projection (tensor cores)
    gemm_bf16x3<<<dim3(HID / 128, MROWS / 128), 128, GEMM_SMEM>>>(ath, atl, woh, wol, out, HID, HID);
}

// round 10
// speedup vs baseline: 1.0669x; 1.0669x over previous
#include <cuda_runtime.h>
#include <cuda_bf16.h>
#include <math.h>
#include <cstdint>

#define B_    2
#define S_    2048
#define HID   2048
#define HQ    16
#define HKV   4
#define D_    128
#define MROWS (B_ * S_)      // 4096
#define KVW   (HKV * D_)     // 512

// ---------------- scratch (allocation-free: __device__ globals) ----------------
__device__ float g_qproj[(size_t)MROWS * HID];
__device__ float g_kproj[(size_t)MROWS * KVW];
__device__ float g_vproj[(size_t)MROWS * KVW];
__device__ float g_gate [(size_t)MROWS * HID];

// q/k/v in bf16 hi/lo, [b][h][s][d]
__device__ __nv_bfloat16 g_qh[(size_t)B_ * HQ  * S_ * D_];
__device__ __nv_bfloat16 g_ql[(size_t)B_ * HQ  * S_ * D_];
__device__ __nv_bfloat16 g_kh[(size_t)B_ * HKV * S_ * D_];
__device__ __nv_bfloat16 g_kl[(size_t)B_ * HKV * S_ * D_];
__device__ __nv_bfloat16 g_vh[(size_t)B_ * HKV * S_ * D_];
__device__ __nv_bfloat16 g_vl[(size_t)B_ * HKV * S_ * D_];

// bf16 hi/lo splits for GEMMs
__device__ __nv_bfloat16 g_hs_hi[(size_t)MROWS * HID];
__device__ __nv_bfloat16 g_hs_lo[(size_t)MROWS * HID];
__device__ __nv_bfloat16 g_wq_hi[(size_t)HID * HID];
__device__ __nv_bfloat16 g_wq_lo[(size_t)HID * HID];
__device__ __nv_bfloat16 g_wk_hi[(size_t)KVW * HID];
__device__ __nv_bfloat16 g_wk_lo[(size_t)KVW * HID];
__device__ __nv_bfloat16 g_wv_hi[(size_t)KVW * HID];
__device__ __nv_bfloat16 g_wv_lo[(size_t)KVW * HID];
__device__ __nv_bfloat16 g_wg_hi[(size_t)HID * HID];
__device__ __nv_bfloat16 g_wg_lo[(size_t)HID * HID];
__device__ __nv_bfloat16 g_wo_hi[(size_t)HID * HID];
__device__ __nv_bfloat16 g_wo_lo[(size_t)HID * HID];
__device__ __nv_bfloat16 g_at_hi[(size_t)MROWS * HID];
__device__ __nv_bfloat16 g_at_lo[(size_t)MROWS * HID];

// ---------------- PTX helpers (base sm_100-safe) ----------------
__device__ __forceinline__ uint32_t smem_u32(const void* p) {
    return (uint32_t)__cvta_generic_to_shared(p);
}
#define CP16(dst, src) \
    asm volatile("cp.async.cg.shared.global [%0], [%1], 16;\n" :: "r"(dst), "l"(src))
#define CP_COMMIT() asm volatile("cp.async.commit_group;\n" ::: "memory")
#define CP_WAIT(n)  asm volatile("cp.async.wait_group %0;\n" :: "n"(n) : "memory")

#define LDMX4(r, addr) \
    asm volatile("ldmatrix.sync.aligned.m8n8.x4.shared.b16 {%0,%1,%2,%3}, [%4];" \
        : "=r"((r)[0]), "=r"((r)[1]), "=r"((r)[2]), "=r"((r)[3]) : "r"(addr))
#define LDMX4T(r, addr) \
    asm volatile("ldmatrix.sync.aligned.m8n8.x4.trans.shared.b16 {%0,%1,%2,%3}, [%4];" \
        : "=r"((r)[0]), "=r"((r)[1]), "=r"((r)[2]), "=r"((r)[3]) : "r"(addr))

#define MMA16816(d, a, b) \
    asm volatile("mma.sync.aligned.m16n8k16.row.col.f32.bf16.bf16.f32 " \
        "{%0,%1,%2,%3}, {%4,%5,%6,%7}, {%8,%9}, {%0,%1,%2,%3};" \
        : "+f"((d)[0]), "+f"((d)[1]), "+f"((d)[2]), "+f"((d)[3]) \
        : "r"((a)[0]), "r"((a)[1]), "r"((a)[2]), "r"((a)[3]), "r"((b)[0]), "r"((b)[1]))

__device__ __forceinline__ float fexp2(float x) {
    float y; asm("ex2.approx.ftz.f32 %0, %1;" : "=f"(y) : "f"(x)); return y;
}

// ---------------- split: fp32 -> (bf16 hi, bf16 lo) ----------------
__global__ void __launch_bounds__(256) split_bf16(const float* __restrict__ x,
                                                  __nv_bfloat16* __restrict__ hi,
                                                  __nv_bfloat16* __restrict__ lo, int n)
{
    int i = (blockIdx.x * blockDim.x + threadIdx.x) * 4;
    if (i >= n) return;
    float4 v = *(const float4*)(x + i);
    float vv[4] = {v.x, v.y, v.z, v.w};
    __nv_bfloat162 h[2], l[2];
#pragma unroll
    for (int j = 0; j < 2; ++j) {
        __nv_bfloat16 a = __float2bfloat16(vv[2 * j]);
        __nv_bfloat16 b = __float2bfloat16(vv[2 * j + 1]);
        h[j] = __nv_bfloat162(a, b);
        l[j] = __nv_bfloat162(__float2bfloat16(vv[2 * j]     - __bfloat162float(a)),
                              __float2bfloat16(vv[2 * j + 1] - __bfloat162float(b)));
    }
    *(uint2*)(hi + i) = *(const uint2*)h;
    *(uint2*)(lo + i) = *(const uint2*)l;
}

// ---------------- mma.sync bf16x3 GEMM body: warp tile 64x64, CTA 128x128 ----------------
// 128 threads (4 warps, 2Mx2N), BK=32, rows padded to 80B, cp.async double buffer, 2 CTAs/SM.
// Inner loop restructured into 3 product passes (hi*hi, hi*lo, lo*hi) so the three MMAs
// that accumulate into the same register are 32 instructions apart (latency hidden).
#define BK     32
#define ROWB   80
#define OPB    (128 * ROWB)         // 10240
#define STG    (4 * OPB)            // 40960 (Ahi, Alo, Bhi, Blo)
#define GEMM_SMEM (2 * STG)         // 81920

__device__ __forceinline__ void gemm_body(
    const __nv_bfloat16* __restrict__ Ahi, const __nv_bfloat16* __restrict__ Alo,
    const __nv_bfloat16* __restrict__ Bhi, const __nv_bfloat16* __restrict__ Blo,
    float* __restrict__ C, int N, int K, int bm, int bn, char* smem)
{
    const uint32_t sb = smem_u32(smem);
    const int tid  = threadIdx.x;
    const int wid  = tid >> 5, lane = tid & 31;
    const int wm   = wid & 1;          // 2 warps in M: 64 rows each
    const int wn   = wid >> 1;         // 2 warps in N: 64 cols each

    const uint32_t a_off = (uint32_t)((lane & 15) * ROWB + (lane >> 4) * 16);
    const uint32_t b_off = (uint32_t)((lane & 7) * ROWB + ((lane >> 4) & 1) * (8 * ROWB)
                                      + ((lane >> 3) & 1) * 16);

    float acc[4][8][4];
#pragma unroll
    for (int i = 0; i < 4; ++i)
#pragma unroll
        for (int j = 0; j < 8; ++j)
#pragma unroll
            for (int v = 0; v < 4; ++v) acc[i][j][v] = 0.f;

    const int T = K / BK;

#define FILL(s, kt) do {                                                          \
        uint32_t base = sb + (uint32_t)(s) * STG;                                 \
        int k0 = (kt) * BK;                                                       \
        _Pragma("unroll")                                                         \
        for (int c = 0; c < 4; ++c) {                                             \
            int chunk = c * 128 + tid;                                            \
            int r = chunk >> 2, o16 = (chunk & 3) * 16;                           \
            uint32_t so = (uint32_t)(r * ROWB + o16);                             \
            const char* pah = (const char*)(Ahi + (size_t)(bm + r) * K + k0) + o16; \
            const char* pal = (const char*)(Alo + (size_t)(bm + r) * K + k0) + o16; \
            const char* pbh = (const char*)(Bhi + (size_t)(bn + r) * K + k0) + o16; \
            const char* pbl = (const char*)(Blo + (size_t)(bn + r) * K + k0) + o16; \
            CP16(base + so,           pah);                                       \
            CP16(base + OPB + so,     pal);                                       \
            CP16(base + 2 * OPB + so, pbh);                                       \
            CP16(base + 3 * OPB + so, pbl);                                       \
        }                                                                         \
    } while (0)

    FILL(0, 0); CP_COMMIT();

    for (int t = 0; t < T; ++t) {
        const int s = t & 1;
        if (t + 1 < T) { FILL(s ^ 1, t + 1); CP_COMMIT(); CP_WAIT(1); }
        else           { CP_WAIT(0); }
        __syncthreads();

        const uint32_t abase = sb + (uint32_t)s * STG + (uint32_t)(wm * 64) * ROWB;
        const uint32_t bbase = sb + (uint32_t)s * STG + 2 * OPB + (uint32_t)(wn * 64) * ROWB;

#pragma unroll
        for (int ks = 0; ks < 2; ++ks) {
            uint32_t ah[4][4], al[4][4], bh[4][4], bl[4][4];
#pragma unroll
            for (int mi = 0; mi < 4; ++mi) {
                uint32_t aa = abase + (uint32_t)(mi * 16) * ROWB + a_off + ks * 32;
                LDMX4(ah[mi], aa);
                LDMX4(al[mi], aa + OPB);
            }
#pragma unroll
            for (int p = 0; p < 4; ++p) {
                uint32_t ba = bbase + (uint32_t)(p * 16) * ROWB + b_off + ks * 32;
                LDMX4(bh[p], ba);
                LDMX4(bl[p], ba + OPB);
            }
            // pass 1: hi*hi (32 MMAs, each acc touched once)
#pragma unroll
            for (int mi = 0; mi < 4; ++mi)
#pragma unroll
                for (int p = 0; p < 4; ++p) {
                    MMA16816(acc[mi][2 * p],     ah[mi], bh[p]);
                    MMA16816(acc[mi][2 * p + 1], ah[mi], bh[p] + 2);
                }
            // pass 2: hi*lo
#pragma unroll
            for (int mi = 0; mi < 4; ++mi)
#pragma unroll
                for (int p = 0; p < 4; ++p) {
                    MMA16816(acc[mi][2 * p],     ah[mi], bl[p]);
                    MMA16816(acc[mi][2 * p + 1], ah[mi], bl[p] + 2);
                }
            // pass 3: lo*hi
#pragma unroll
            for (int mi = 0; mi < 4; ++mi)
#pragma unroll
                for (int p = 0; p < 4; ++p) {
                    MMA16816(acc[mi][2 * p],     al[mi], bh[p]);
                    MMA16816(acc[mi][2 * p + 1], al[mi], bh[p] + 2);
                }
        }
        __syncthreads();
    }

    const int r0 = bm + wm * 64 + (lane >> 2);
    const int c0 = bn + wn * 64 + (lane & 3) * 2;
#pragma unroll
    for (int mi = 0; mi < 4; ++mi)
#pragma unroll
        for (int ni = 0; ni < 8; ++ni) {
            int row = r0 + mi * 16;
            int col = c0 + ni * 8;
            *(float2*)(C + (size_t)row * N + col)       = make_float2(acc[mi][ni][0], acc[mi][ni][1]);
            *(float2*)(C + (size_t)(row + 8) * N + col) = make_float2(acc[mi][ni][2], acc[mi][ni][3]);
        }
#undef FILL
}

// fused Q/K/V/G projections: grid.x = 16(Q)+4(K)+4(V)+16(G) = 40, grid.y = 32
__global__ void __launch_bounds__(128, 2) gemm_qkvg()
{
    extern __shared__ char smem[];
    const int bx = blockIdx.x;
    const int bm = blockIdx.y * 128;
    const __nv_bfloat16 *Bh, *Bl;
    float* C;
    int N, bn;
    if (bx < 16)      { Bh = g_wq_hi; Bl = g_wq_lo; C = g_qproj; N = HID; bn = bx * 128; }
    else if (bx < 20) { Bh = g_wk_hi; Bl = g_wk_lo; C = g_kproj; N = KVW; bn = (bx - 16) * 128; }
    else if (bx < 24) { Bh = g_wv_hi; Bl = g_wv_lo; C = g_vproj; N = KVW; bn = (bx - 20) * 128; }
    else              { Bh = g_wg_hi; Bl = g_wg_lo; C = g_gate;  N = HID; bn = (bx - 24) * 128; }
    gemm_body(g_hs_hi, g_hs_lo, Bh, Bl, C, N, HID, bm, bn, smem);
}

// generic GEMM (used for the Wo projection)
__global__ void __launch_bounds__(128, 2)
gemm_bf16x3(const __nv_bfloat16* __restrict__ Ahi, const __nv_bfloat16* __restrict__ Alo,
            const __nv_bfloat16* __restrict__ Bhi, const __nv_bfloat16* __restrict__ Blo,
            float* __restrict__ C, int N, int K)
{
    extern __shared__ char smem[];
    gemm_body(Ahi, Alo, Bhi, Blo, C, N, K, blockIdx.y * 128, blockIdx.x * 128, smem);
}

// ---------------- fused RMSNorm + RoPE + transpose -> bf16 hi/lo ----------------
__device__ __forceinline__ void st_hilo(__nv_bfloat16* ph, __nv_bfloat16* pl, float v) {
    __nv_bfloat16 h = __float2bfloat16(v);
    *ph = h;
    *pl = __float2bfloat16(v - __bfloat162float(h));
}

__global__ void __launch_bounds__(256) rope_norm_kernel(const float* __restrict__ cosT,
                                                        const float* __restrict__ sinT,
                                                        const float* __restrict__ qw,
                                                        const float* __restrict__ kw)
{
    const int gw   = (blockIdx.x * blockDim.x + threadIdx.x) >> 5;
    const int lane = threadIdx.x & 31;
    const int NQ = MROWS * HQ;
    const int NK = MROWS * HKV;

    if (gw < NQ + NK) {
        bool isq = (gw < NQ);
        int idx = isq ? gw : gw - NQ;
        int nh  = isq ? HQ : HKV;
        int h = idx % nh;
        int m = idx / nh;
        int s = m % S_, b = m / S_;
        const float* x = (isq ? g_qproj + (size_t)m * HID : g_kproj + (size_t)m * KVW) + h * D_;
        const float* w = isq ? qw : kw;

        float x0 = x[lane], x1 = x[lane + 32], x2 = x[lane + 64], x3 = x[lane + 96];
        float ss = x0 * x0 + x1 * x1 + x2 * x2 + x3 * x3;
#pragma unroll
        for (int off = 16; off; off >>= 1) ss += __shfl_xor_sync(0xffffffffu, ss, off);
        float r = rsqrtf(ss * (1.f / 128.f) + 1e-6f);
        x0 = x0 * r * w[lane];
        x1 = x1 * r * w[lane + 32];
        x2 = x2 * r * w[lane + 64];
        x3 = x3 * r * w[lane + 96];

        const float* c  = cosT + (size_t)s * D_;
        const float* sn = sinT + (size_t)s * D_;
        float o0 = x0 * c[lane]      - x2 * sn[lane];
        float o1 = x1 * c[lane + 32] - x3 * sn[lane + 32];
        float o2 = x2 * c[lane + 64] + x0 * sn[lane + 64];
        float o3 = x3 * c[lane + 96] + x1 * sn[lane + 96];

        size_t base = isq ? (size_t)((b * HQ + h) * S_ + s) * D_
                          : (size_t)((b * HKV + h) * S_ + s) * D_;
        __nv_bfloat16* oh = isq ? g_qh + base : g_kh + base;
        __nv_bfloat16* ol = isq ? g_ql + base : g_kl + base;
        st_hilo(oh + lane,      ol + lane,      o0);
        st_hilo(oh + lane + 32, ol + lane + 32, o1);
        st_hilo(oh + lane + 64, ol + lane + 64, o2);
        st_hilo(oh + lane + 96, ol + lane + 96, o3);
    } else if (gw < NQ + 2 * NK) {
        int vi = gw - NQ - NK;
        int h = vi % HKV;
        int m = vi / HKV;
        int s = m % S_, b = m / S_;
        const float* x = g_vproj + (size_t)m * KVW + h * D_;
        size_t base = (size_t)((b * HKV + h) * S_ + s) * D_;
        st_hilo(g_vh + base + lane,      g_vl + base + lane,      x[lane]);
        st_hilo(g_vh + base + lane + 32, g_vl + base + lane + 32, x[lane + 32]);
        st_hilo(g_vh + base + lane + 64, g_vl + base + lane + 64, x[lane + 64]);
        st_hilo(g_vh + base + lane + 96, g_vl + base + lane + 96, x[lane + 96]);
    }
}

// ---------------- tensor-core flash attention (causal, bf16x3) ----------------
#define QR    128
#define KT    64
#define DSTR  272
#define QARR  (QR * DSTR)
#define KARR  (KT * DSTR)
#define KVSTG (4 * KARR)
#define ATTN_SMEM (2 * QARR + 2 * KVSTG)   // 208896

__global__ void __launch_bounds__(256) attn_tc(const float* __restrict__ gate)
{
    extern __shared__ char smc[];
    const uint32_t sb = smem_u32(smc);
    const int tid = threadIdx.x;
    const int wid = tid >> 5, lane = tid & 31;
    const int bh = blockIdx.y;
    const int b = bh >> 4, h = bh & 15;
    const int kvh = h >> 2;
    const int qt = gridDim.x - 1 - blockIdx.x;
    const int q0 = qt * QR;

    const char* Qh_g = (const char*)(g_qh + ((size_t)(b * HQ + h) * S_ + q0) * D_);
    const char* Ql_g = (const char*)(g_ql + ((size_t)(b * HQ + h) * S_ + q0) * D_);
    const char* Kh_g = (const char*)(g_kh + (size_t)(b * HKV + kvh) * S_ * D_);
    const char* Kl_g = (const char*)(g_kl + (size_t)(b * HKV + kvh) * S_ * D_);
    const char* Vh_g = (const char*)(g_vh + (size_t)(b * HKV + kvh) * S_ * D_);
    const char* Vl_g = (const char*)(g_vl + (size_t)(b * HKV + kvh) * S_ * D_);

    const int T = q0 / KT + 2;

#define KVFILL(s, t) do {                                                   \
        uint32_t base = sb + 2 * QARR + (uint32_t)(s) * KVSTG;              \
        size_t gk = (size_t)(t) * KT * 256;                                 \
        _Pragma("unroll")                                                   \
        for (int c = 0; c < 4; ++c) {                                       \
            int idx = c * 256 + tid;                                        \
            int r = idx >> 4, o16 = (idx & 15) * 16;                        \
            uint32_t so = (uint32_t)(r * DSTR + o16);                       \
            size_t gb = gk + (size_t)r * 256 + o16;                         \
            CP16(base + so,            Kh_g + gb);                          \
            CP16(base + KARR + so,     Kl_g + gb);                          \
            CP16(base + 2 * KARR + so, Vh_g + gb);                          \
            CP16(base + 3 * KARR + so, Vl_g + gb);                          \
        }                                                                   \
    } while (0)

    {
#pragma unroll
        for (int c = 0; c < 8; ++c) {
            int idx = c * 256 + tid;
            int r = idx >> 4, o16 = (idx & 15) * 16;
            uint32_t so = (uint32_t)(r * DSTR + o16);
            size_t gb = (size_t)r * 256 + o16;
            CP16(sb + so,        Qh_g + gb);
            CP16(sb + QARR + so, Ql_g + gb);
        }
        KVFILL(0, 0); CP_COMMIT();
        KVFILL(1, 1); CP_COMMIT();
    }

    const uint32_t a_off = (uint32_t)((lane & 15) * DSTR + (lane >> 4) * 16);
    const uint32_t b_off = (uint32_t)((lane & 7) * DSTR + ((lane >> 4) & 1) * (8 * DSTR)
                                      + ((lane >> 3) & 1) * 16);
    const uint32_t qbase = sb + (uint32_t)(wid * 16) * DSTR;

    float o[16][4];
#pragma unroll
    for (int j = 0; j < 16; ++j)
#pragma unroll
        for (int v = 0; v < 4; ++v) o[j][v] = 0.f;
    float mi[2] = {-1e30f, -1e30f};
    float li[2] = {0.f, 0.f};

    const float SC = 0.08838834764831845f * 1.4426950408889634f;

    for (int t = 0; t < T; ++t) {
        const int s = t & 1;
        if (t + 1 < T) CP_WAIT(1); else CP_WAIT(0);
        __syncthreads();

        const uint32_t kbase = sb + 2 * QARR + (uint32_t)s * KVSTG;
        const uint32_t vbase = kbase + 2 * KARR;

        // ---- S = Q K^T (bf16x3), 3 product passes to break acc chains ----
        float sc[8][4];
#pragma unroll
        for (int j = 0; j < 8; ++j)
#pragma unroll
            for (int v = 0; v < 4; ++v) sc[j][v] = 0.f;

#pragma unroll
        for (int kk = 0; kk < 8; ++kk) {
            uint32_t ah[4], al[4], kh[4][4], kl[4][4];
            uint32_t aa = qbase + a_off + kk * 32;
            LDMX4(ah, aa);
            LDMX4(al, aa + QARR);
#pragma unroll
            for (int p = 0; p < 4; ++p) {
                uint32_t ba = kbase + (uint32_t)(p * 16) * DSTR + b_off + kk * 32;
                LDMX4(kh[p], ba);
                LDMX4(kl[p], ba + KARR);
            }
#pragma unroll
            for (int p = 0; p < 4; ++p) {
                MMA16816(sc[2 * p],     ah, kh[p]);
                MMA16816(sc[2 * p + 1], ah, kh[p] + 2);
            }
#pragma unroll
            for (int p = 0; p < 4; ++p) {
                MMA16816(sc[2 * p],     ah, kl[p]);
                MMA16816(sc[2 * p + 1], ah, kl[p] + 2);
            }
#pragma unroll
            for (int p = 0; p < 4; ++p) {
                MMA16816(sc[2 * p],     al, kh[p]);
                MMA16816(sc[2 * p + 1], al, kh[p] + 2);
            }
        }

        const int k0 = t * KT;
        const bool tail = (t + 2 >= T);
#pragma unroll
        for (int tl = 0; tl < 8; ++tl)
#pragma unroll
            for (int v = 0; v < 4; ++v) {
                float x = sc[tl][v] * SC;
                if (tail) {
                    int col = k0 + tl * 8 + (lane & 3) * 2 + (v & 1);
                    int row = q0 + wid * 16 + (lane >> 2) + ((v >> 1) << 3);
                    if (col > row) x = -1e30f;
                }
                sc[tl][v] = x;
            }

        uint32_t PH0[8], PH1[8], PL0[8], PL1[8];
#pragma unroll
        for (int hh = 0; hh < 2; ++hh) {
            float rm = -1e30f;
#pragma unroll
            for (int tl = 0; tl < 8; ++tl)
                rm = fmaxf(rm, fmaxf(sc[tl][2 * hh], sc[tl][2 * hh + 1]));
            rm = fmaxf(rm, __shfl_xor_sync(0xffffffffu, rm, 1));
            rm = fmaxf(rm, __shfl_xor_sync(0xffffffffu, rm, 2));
            float mnew = fmaxf(mi[hh], rm);
            float corr = fexp2(mi[hh] - mnew);
            float rs = 0.f;
#pragma unroll
            for (int tl = 0; tl < 8; ++tl) {
                float p0 = fexp2(sc[tl][2 * hh]     - mnew);
                float p1 = fexp2(sc[tl][2 * hh + 1] - mnew);
                rs += p0 + p1;
                __nv_bfloat16 b0 = __float2bfloat16(p0), b1 = __float2bfloat16(p1);
                __nv_bfloat162 hp(b0, b1);
                float l0 = p0 - __bfloat162float(b0);
                float l1 = p1 - __bfloat162float(b1);
                __nv_bfloat162 lp(__float2bfloat16(l0), __float2bfloat16(l1));
                if (hh == 0) { PH0[tl] = *(uint32_t*)&hp; PL0[tl] = *(uint32_t*)&lp; }
                else         { PH1[tl] = *(uint32_t*)&hp; PL1[tl] = *(uint32_t*)&lp; }
            }
            rs += __shfl_xor_sync(0xffffffffu, rs, 1);
            rs += __shfl_xor_sync(0xffffffffu, rs, 2);
            li[hh] = li[hh] * corr + rs;
            mi[hh] = mnew;
#pragma unroll
            for (int j = 0; j < 16; ++j) {
                o[j][2 * hh]     *= corr;
                o[j][2 * hh + 1] *= corr;
            }
        }

        // ---- O += P V (bf16x3), two half-passes of 4 N-tiles, 3 product passes each ----
#pragma unroll
        for (int kk2 = 0; kk2 < 4; ++kk2) {
            uint32_t ph[4] = {PH0[2 * kk2], PH1[2 * kk2], PH0[2 * kk2 + 1], PH1[2 * kk2 + 1]};
            uint32_t pl[4] = {PL0[2 * kk2], PL1[2 * kk2], PL0[2 * kk2 + 1], PL1[2 * kk2 + 1]};
#pragma unroll
            for (int half = 0; half < 2; ++half) {
                uint32_t vh[4][4], vl[4][4];
#pragma unroll
                for (int p = 0; p < 4; ++p) {
                    uint32_t va = vbase + (uint32_t)(kk2 * 16) * DSTR + a_off
                                + (half * 4 + p) * 32;
                    LDMX4T(vh[p], va);
                    LDMX4T(vl[p], va + KARR);
                }
#pragma unroll
                for (int p = 0; p < 4; ++p) {
                    int q = half * 4 + p;
                    MMA16816(o[2 * q],     ph, vh[p]);
                    MMA16816(o[2 * q + 1], ph, vh[p] + 2);
                }
#pragma unroll
                for (int p = 0; p < 4; ++p) {
                    int q = half * 4 + p;
                    MMA16816(o[2 * q],     ph, vl[p]);
                    MMA16816(o[2 * q + 1], ph, vl[p] + 2);
                }
#pragma unroll
                for (int p = 0; p < 4; ++p) {
                    int q = half * 4 + p;
                    MMA16816(o[2 * q],     pl, vh[p]);
                    MMA16816(o[2 * q + 1], pl, vh[p] + 2);
                }
            }
        }

        __syncthreads();
        if (t + 2 < T) { KVFILL(s, t + 2); CP_COMMIT(); }
    }

#pragma unroll
    for (int hh = 0; hh < 2; ++hh) {
        int row = q0 + wid * 16 + (lane >> 2) + hh * 8;
        size_t m = (size_t)b * S_ + row;
        float inv = 1.f / li[hh];
        const float* gr = gate + m * HID + h * D_;
        __nv_bfloat16* oh = g_at_hi + m * HID + h * D_;
        __nv_bfloat16* ol = g_at_lo + m * HID + h * D_;
#pragma unroll
        for (int j = 0; j < 16; ++j) {
            int d0 = j * 8 + (lane & 3) * 2;
            float2 gv = *(const float2*)(gr + d0);
            float s0 = 1.f / (1.f + fexp2(-gv.x * 1.4426950408889634f));
            float s1 = 1.f / (1.f + fexp2(-gv.y * 1.4426950408889634f));
            float v0 = o[j][2 * hh]     * inv * s0;
            float v1 = o[j][2 * hh + 1] * inv * s1;
            __nv_bfloat16 h0 = __float2bfloat16(v0), h1 = __float2bfloat16(v1);
            __nv_bfloat162 hp(h0, h1);
            __nv_bfloat162 lp(__float2bfloat16(v0 - __bfloat162float(h0)),
                              __float2bfloat16(v1 - __bfloat162float(h1)));
            *(__nv_bfloat162*)(oh + d0) = hp;
            *(__nv_bfloat162*)(ol + d0) = lp;
        }
    }
#undef KVFILL
}

// ---------------- launch ----------------
extern "C" void kernel_launch(void* const* d_in, const int* in_sizes, int n_in,
                              void* d_out, int out_size)
{
    const float* hs   = (const float*)d_in[0];
    const float* cosT = (const float*)d_in[1];
    const float* sinT = (const float*)d_in[2];
    const float* Wq   = (const float*)d_in[3];
    const float* Wk   = (const float*)d_in[4];
    const float* Wv   = (const float*)d_in[5];
    const float* Wg   = (const float*)d_in[6];
    const float* Wo   = (const float*)d_in[7];
    const float* qw   = (const float*)d_in[8];
    const float* kw   = (const float*)d_in[9];
    float* out = (float*)d_out;

    float* gp;
    cudaGetSymbolAddress((void**)&gp, g_gate);

    __nv_bfloat16 *hsh, *hsl, *wqh, *wql, *wkh, *wkl, *wvh, *wvl, *wgh, *wgl, *woh, *wol, *ath, *atl;
    cudaGetSymbolAddress((void**)&hsh, g_hs_hi); cudaGetSymbolAddress((void**)&hsl, g_hs_lo);
    cudaGetSymbolAddress((void**)&wqh, g_wq_hi); cudaGetSymbolAddress((void**)&wql, g_wq_lo);
    cudaGetSymbolAddress((void**)&wkh, g_wk_hi); cudaGetSymbolAddress((void**)&wkl, g_wk_lo);
    cudaGetSymbolAddress((void**)&wvh, g_wv_hi); cudaGetSymbolAddress((void**)&wvl, g_wv_lo);
    cudaGetSymbolAddress((void**)&wgh, g_wg_hi); cudaGetSymbolAddress((void**)&wgl, g_wg_lo);
    cudaGetSymbolAddress((void**)&woh, g_wo_hi); cudaGetSymbolAddress((void**)&wol, g_wo_lo);
    cudaGetSymbolAddress((void**)&ath, g_at_hi); cudaGetSymbolAddress((void**)&atl, g_at_lo);

    cudaFuncSetAttribute(gemm_qkvg,   cudaFuncAttributeMaxDynamicSharedMemorySize, GEMM_SMEM);
    cudaFuncSetAttribute(gemm_bf16x3, cudaFuncAttributeMaxDynamicSharedMemorySize, GEMM_SMEM);
    cudaFuncSetAttribute(attn_tc,     cudaFuncAttributeMaxDynamicSharedMemorySize, ATTN_SMEM);

    // fp32 -> bf16 hi/lo splits
    const int nHS = MROWS * HID, nSq = HID * HID, nKv = KVW * HID;
    split_bf16<<<nHS / 1024, 256>>>(hs, hsh, hsl, nHS);
    split_bf16<<<nSq / 1024, 256>>>(Wq, wqh, wql, nSq);
    split_bf16<<<nKv / 1024, 256>>>(Wk, wkh, wkl, nKv);
    split_bf16<<<nKv / 1024, 256>>>(Wv, wvh, wvl, nKv);
    split_bf16<<<nSq / 1024, 256>>>(Wg, wgh, wgl, nSq);
    split_bf16<<<nSq / 1024, 256>>>(Wo, woh, wol, nSq);

    // fused Q/K/V/G projections (tensor cores, bf16x3, latency-hidden MMA schedule)
    gemm_qkvg<<<dim3(40, MROWS / 128), 128, GEMM_SMEM>>>();

    // RMSNorm + RoPE + transpose -> bf16 hi/lo q/k/v
    {
        int total_warps = MROWS * (HQ + 2 * HKV);
        rope_norm_kernel<<<total_warps / 8, 256>>>(cosT, sinT, qw, kw);
    }

    // tensor-core causal flash attention + gated epilogue
    attn_tc<<<dim3(S_ / QR, B_ * HQ), 256, ATTN_SMEM>>>(gp);

    // output projection (tensor cores)
    gemm_bf16x3<<<dim3(HID / 128, MROWS / 128), 128, GEMM_SMEM>>>(ath, atl, woh, wol, out, HID, HID);
}

// round 11
// speedup vs baseline: 2.4093x; 2.2582x over previous
#include <cuda_runtime.h>
#include <cuda_fp16.h>
#include <math.h>
#include <cstdint>

#define B_    2
#define S_    2048
#define HID   2048
#define HQ    16
#define HKV   4
#define D_    128
#define MROWS (B_ * S_)      // 4096
#define KVW   (HKV * D_)     // 512

// ---------------- scratch (allocation-free: __device__ globals) ----------------
__device__ float g_qproj[(size_t)MROWS * HID];
__device__ float g_kproj[(size_t)MROWS * KVW];
__device__ float g_vproj[(size_t)MROWS * KVW];
__device__ float g_gate [(size_t)MROWS * HID];

// fp16 operands
__device__ __half g_hs[(size_t)MROWS * HID];
__device__ __half g_wq[(size_t)HID * HID];
__device__ __half g_wk[(size_t)KVW * HID];
__device__ __half g_wv[(size_t)KVW * HID];
__device__ __half g_wg[(size_t)HID * HID];
__device__ __half g_wo[(size_t)HID * HID];
__device__ __half g_at[(size_t)MROWS * HID];

// q/k/v fp16, [b][h][s][d]
__device__ __half g_q[(size_t)B_ * HQ  * S_ * D_];
__device__ __half g_k[(size_t)B_ * HKV * S_ * D_];
__device__ __half g_v[(size_t)B_ * HKV * S_ * D_];

// ---------------- PTX helpers (base sm_100-safe) ----------------
__device__ __forceinline__ uint32_t smem_u32(const void* p) {
    return (uint32_t)__cvta_generic_to_shared(p);
}
#define CP16(dst, src) \
    asm volatile("cp.async.cg.shared.global [%0], [%1], 16;\n" :: "r"(dst), "l"(src))
#define CP_COMMIT() asm volatile("cp.async.commit_group;\n" ::: "memory")
#define CP_WAIT(n)  asm volatile("cp.async.wait_group %0;\n" :: "n"(n) : "memory")

#define LDMX4(r, addr) \
    asm volatile("ldmatrix.sync.aligned.m8n8.x4.shared.b16 {%0,%1,%2,%3}, [%4];" \
        : "=r"((r)[0]), "=r"((r)[1]), "=r"((r)[2]), "=r"((r)[3]) : "r"(addr))
#define LDMX4T(r, addr) \
    asm volatile("ldmatrix.sync.aligned.m8n8.x4.trans.shared.b16 {%0,%1,%2,%3}, [%4];" \
        : "=r"((r)[0]), "=r"((r)[1]), "=r"((r)[2]), "=r"((r)[3]) : "r"(addr))

#define MMAH(d, a, b) \
    asm volatile("mma.sync.aligned.m16n8k16.row.col.f32.f16.f16.f32 " \
        "{%0,%1,%2,%3}, {%4,%5,%6,%7}, {%8,%9}, {%0,%1,%2,%3};" \
        : "+f"((d)[0]), "+f"((d)[1]), "+f"((d)[2]), "+f"((d)[3]) \
        : "r"((a)[0]), "r"((a)[1]), "r"((a)[2]), "r"((a)[3]), "r"((b)[0]), "r"((b)[1]))

__device__ __forceinline__ float fexp2(float x) {
    float y; asm("ex2.approx.ftz.f32 %0, %1;" : "=f"(y) : "f"(x)); return y;
}

// ---------------- convert: fp32 -> fp16 ----------------
__global__ void __launch_bounds__(256) to_half(const float* __restrict__ x,
                                               __half* __restrict__ y, int n)
{
    int i = (blockIdx.x * blockDim.x + threadIdx.x) * 4;
    if (i >= n) return;
    float4 v = *(const float4*)(x + i);
    __half2 h0 = __floats2half2_rn(v.x, v.y);
    __half2 h1 = __floats2half2_rn(v.z, v.w);
    *(__half2*)(y + i)     = h0;
    *(__half2*)(y + i + 2) = h1;
}

// ---------------- fp16 mma.sync GEMM: C[m][n] = sum_k A[m][k]*B[n][k] ----------------
// CTA 128x128, warp tile 64x64 (4 warps, 2Mx2N), BK=64, rows 144B (128 data + 16 pad,
// conflict-free ldmatrix), cp.async double buffer, 2 CTAs/SM.
#define BK     64
#define ROWB   144
#define OPB    (128 * ROWB)         // 18432
#define STG    (2 * OPB)            // 36864 (A, B)
#define GEMM_SMEM (2 * STG)         // 73728

__device__ __forceinline__ void gemm_body(
    const __half* __restrict__ A, const __half* __restrict__ B,
    float* __restrict__ C, int N, int K, int bm, int bn, char* smem)
{
    const uint32_t sb = smem_u32(smem);
    const int tid  = threadIdx.x;
    const int wid  = tid >> 5, lane = tid & 31;
    const int wm   = wid & 1;          // 2 warps in M: 64 rows each
    const int wn   = wid >> 1;         // 2 warps in N: 64 cols each

    const uint32_t a_off = (uint32_t)((lane & 15) * ROWB + (lane >> 4) * 16);
    const uint32_t b_off = (uint32_t)((lane & 7) * ROWB + ((lane >> 4) & 1) * (8 * ROWB)
                                      + ((lane >> 3) & 1) * 16);

    float acc[4][8][4];
#pragma unroll
    for (int i = 0; i < 4; ++i)
#pragma unroll
        for (int j = 0; j < 8; ++j)
#pragma unroll
            for (int v = 0; v < 4; ++v) acc[i][j][v] = 0.f;

    const int T = K / BK;

    // fill stage s with K-tile kt: 2 operands x 128 rows x 8 16B-chunks = 2048 cp.asyncs
#define FILL(s, kt) do {                                                          \
        uint32_t base = sb + (uint32_t)(s) * STG;                                 \
        int k0 = (kt) * BK;                                                       \
        _Pragma("unroll")                                                         \
        for (int c = 0; c < 8; ++c) {                                             \
            int idx = c * 128 + tid;                                              \
            int r = idx >> 3, co = (idx & 7) * 16;                                \
            uint32_t so = (uint32_t)(r * ROWB + co);                              \
            const char* pa = (const char*)(A + (size_t)(bm + r) * K + k0) + co;   \
            const char* pb = (const char*)(B + (size_t)(bn + r) * K + k0) + co;   \
            CP16(base + so,       pa);                                            \
            CP16(base + OPB + so, pb);                                            \
        }                                                                         \
    } while (0)

    FILL(0, 0); CP_COMMIT();

    for (int t = 0; t < T; ++t) {
        const int s = t & 1;
        if (t + 1 < T) { FILL(s ^ 1, t + 1); CP_COMMIT(); CP_WAIT(1); }
        else           { CP_WAIT(0); }
        __syncthreads();

        const uint32_t abase = sb + (uint32_t)s * STG + (uint32_t)(wm * 64) * ROWB;
        const uint32_t bbase = sb + (uint32_t)s * STG + OPB + (uint32_t)(wn * 64) * ROWB;

#pragma unroll
        for (int ks = 0; ks < 4; ++ks) {       // BK=64 -> 4 k16 steps
            uint32_t af[4][4], bf[4][4];
#pragma unroll
            for (int mi = 0; mi < 4; ++mi)
                LDMX4(af[mi], abase + (uint32_t)(mi * 16) * ROWB + a_off + ks * 32);
#pragma unroll
            for (int p = 0; p < 4; ++p)
                LDMX4(bf[p], bbase + (uint32_t)(p * 16) * ROWB + b_off + ks * 32);
#pragma unroll
            for (int mi = 0; mi < 4; ++mi)
#pragma unroll
                for (int p = 0; p < 4; ++p) {
                    MMAH(acc[mi][2 * p],     af[mi], bf[p]);
                    MMAH(acc[mi][2 * p + 1], af[mi], bf[p] + 2);
                }
        }
        __syncthreads();
    }

    const int r0 = bm + wm * 64 + (lane >> 2);
    const int c0 = bn + wn * 64 + (lane & 3) * 2;
#pragma unroll
    for (int mi = 0; mi < 4; ++mi)
#pragma unroll
        for (int ni = 0; ni < 8; ++ni) {
            int row = r0 + mi * 16;
            int col = c0 + ni * 8;
            *(float2*)(C + (size_t)row * N + col)       = make_float2(acc[mi][ni][0], acc[mi][ni][1]);
            *(float2*)(C + (size_t)(row + 8) * N + col) = make_float2(acc[mi][ni][2], acc[mi][ni][3]);
        }
#undef FILL
}

// fused Q/K/V/G projections: grid.x = 16(Q)+4(K)+4(V)+16(G) = 40, grid.y = 32
__global__ void __launch_bounds__(128, 2) gemm_qkvg()
{
    extern __shared__ char smem[];
    const int bx = blockIdx.x;
    const int bm = blockIdx.y * 128;
    const __half* Bp;
    float* C;
    int N, bn;
    if (bx < 16)      { Bp = g_wq; C = g_qproj; N = HID; bn = bx * 128; }
    else if (bx < 20) { Bp = g_wk; C = g_kproj; N = KVW; bn = (bx - 16) * 128; }
    else if (bx < 24) { Bp = g_wv; C = g_vproj; N = KVW; bn = (bx - 20) * 128; }
    else              { Bp = g_wg; C = g_gate;  N = HID; bn = (bx - 24) * 128; }
    gemm_body(g_hs, Bp, C, N, HID, bm, bn, smem);
}

// generic GEMM (Wo projection)
__global__ void __launch_bounds__(128, 2)
gemm_f16(const __half* __restrict__ A, const __half* __restrict__ B,
         float* __restrict__ C, int N, int K)
{
    extern __shared__ char smem[];
    gemm_body(A, B, C, N, K, blockIdx.y * 128, blockIdx.x * 128, smem);
}

// ---------------- fused RMSNorm + RoPE + transpose -> fp16 ----------------
__global__ void __launch_bounds__(256) rope_norm_kernel(const float* __restrict__ cosT,
                                                        const float* __restrict__ sinT,
                                                        const float* __restrict__ qw,
                                                        const float* __restrict__ kw)
{
    const int gw   = (blockIdx.x * blockDim.x + threadIdx.x) >> 5;
    const int lane = threadIdx.x & 31;
    const int NQ = MROWS * HQ;
    const int NK = MROWS * HKV;

    if (gw < NQ + NK) {
        bool isq = (gw < NQ);
        int idx = isq ? gw : gw - NQ;
        int nh  = isq ? HQ : HKV;
        int h = idx % nh;
        int m = idx / nh;
        int s = m % S_, b = m / S_;
        const float* x = (isq ? g_qproj + (size_t)m * HID : g_kproj + (size_t)m * KVW) + h * D_;
        const float* w = isq ? qw : kw;

        float x0 = x[lane], x1 = x[lane + 32], x2 = x[lane + 64], x3 = x[lane + 96];
        float ss = x0 * x0 + x1 * x1 + x2 * x2 + x3 * x3;
#pragma unroll
        for (int off = 16; off; off >>= 1) ss += __shfl_xor_sync(0xffffffffu, ss, off);
        float r = rsqrtf(ss * (1.f / 128.f) + 1e-6f);
        x0 = x0 * r * w[lane];
        x1 = x1 * r * w[lane + 32];
        x2 = x2 * r * w[lane + 64];
        x3 = x3 * r * w[lane + 96];

        const float* c  = cosT + (size_t)s * D_;
        const float* sn = sinT + (size_t)s * D_;
        float o0 = x0 * c[lane]      - x2 * sn[lane];
        float o1 = x1 * c[lane + 32] - x3 * sn[lane + 32];
        float o2 = x2 * c[lane + 64] + x0 * sn[lane + 64];
        float o3 = x3 * c[lane + 96] + x1 * sn[lane + 96];

        size_t base = isq ? (size_t)((b * HQ + h) * S_ + s) * D_
                          : (size_t)((b * HKV + h) * S_ + s) * D_;
        __half* o = (isq ? g_q : g_k) + base;
        o[lane]      = __float2half_rn(o0);
        o[lane + 32] = __float2half_rn(o1);
        o[lane + 64] = __float2half_rn(o2);
        o[lane + 96] = __float2half_rn(o3);
    } else if (gw < NQ + 2 * NK) {
        int vi = gw - NQ - NK;
        int h = vi % HKV;
        int m = vi / HKV;
        int s = m % S_, b = m / S_;
        const float* x = g_vproj + (size_t)m * KVW + h * D_;
        __half* o = g_v + (size_t)((b * HKV + h) * S_ + s) * D_;
        o[lane]      = __float2half_rn(x[lane]);
        o[lane + 32] = __float2half_rn(x[lane + 32]);
        o[lane + 64] = __float2half_rn(x[lane + 64]);
        o[lane + 96] = __float2half_rn(x[lane + 96]);
    }
}

// ---------------- tensor-core flash attention (causal, fp16) ----------------
// CTA: 128 q-rows x 64-wide KV tiles, 8 warps. Row stride 272B (17x16B, conflict-free).
#define QR    128
#define KT    64
#define DSTR  272
#define QARR  (QR * DSTR)        // 34816
#define KARR  (KT * DSTR)        // 17408
#define KVSTG (2 * KARR)         // 34816 (K, V)
#define ATTN_SMEM (QARR + 2 * KVSTG)   // 104448

__global__ void __launch_bounds__(256) attn_tc(const float* __restrict__ gate)
{
    extern __shared__ char smc[];
    const uint32_t sb = smem_u32(smc);
    const int tid = threadIdx.x;
    const int wid = tid >> 5, lane = tid & 31;
    const int bh = blockIdx.y;
    const int b = bh >> 4, h = bh & 15;
    const int kvh = h >> 2;
    const int qt = gridDim.x - 1 - blockIdx.x;   // heavy tiles first
    const int q0 = qt * QR;

    const char* Q_g = (const char*)(g_q + ((size_t)(b * HQ + h) * S_ + q0) * D_);
    const char* K_g = (const char*)(g_k + (size_t)(b * HKV + kvh) * S_ * D_);
    const char* V_g = (const char*)(g_v + (size_t)(b * HKV + kvh) * S_ * D_);

    const int T = q0 / KT + 2;

#define KVFILL(s, t) do {                                                   \
        uint32_t base = sb + QARR + (uint32_t)(s) * KVSTG;                  \
        size_t gk = (size_t)(t) * KT * 256;                                 \
        _Pragma("unroll")                                                   \
        for (int c = 0; c < 4; ++c) {                                       \
            int idx = c * 256 + tid;                                        \
            int r = idx >> 4, o16 = (idx & 15) * 16;                        \
            uint32_t so = (uint32_t)(r * DSTR + o16);                       \
            size_t gb = gk + (size_t)r * 256 + o16;                         \
            CP16(base + so,        K_g + gb);                               \
            CP16(base + KARR + so, V_g + gb);                               \
        }                                                                   \
    } while (0)

    {
#pragma unroll
        for (int c = 0; c < 8; ++c) {
            int idx = c * 256 + tid;
            int r = idx >> 4, o16 = (idx & 15) * 16;
            uint32_t so = (uint32_t)(r * DSTR + o16);
            CP16(sb + so, Q_g + (size_t)r * 256 + o16);
        }
        KVFILL(0, 0); CP_COMMIT();
        KVFILL(1, 1); CP_COMMIT();
    }

    const uint32_t a_off = (uint32_t)((lane & 15) * DSTR + (lane >> 4) * 16);
    const uint32_t b_off = (uint32_t)((lane & 7) * DSTR + ((lane >> 4) & 1) * (8 * DSTR)
                                      + ((lane >> 3) & 1) * 16);
    const uint32_t qbase = sb + (uint32_t)(wid * 16) * DSTR;

    float o[16][4];
#pragma unroll
    for (int j = 0; j < 16; ++j)
#pragma unroll
        for (int v = 0; v < 4; ++v) o[j][v] = 0.f;
    float mi[2] = {-1e30f, -1e30f};
    float li[2] = {0.f, 0.f};

    const float SC = 0.08838834764831845f * 1.4426950408889634f;  // scale * log2(e)

    for (int t = 0; t < T; ++t) {
        const int s = t & 1;
        if (t + 1 < T) CP_WAIT(1); else CP_WAIT(0);
        __syncthreads();

        const uint32_t kbase = sb + QARR + (uint32_t)s * KVSTG;
        const uint32_t vbase = kbase + KARR;

        // ---- S = Q K^T ----
        float sc[8][4];
#pragma unroll
        for (int j = 0; j < 8; ++j)
#pragma unroll
            for (int v = 0; v < 4; ++v) sc[j][v] = 0.f;

#pragma unroll
        for (int kk = 0; kk < 8; ++kk) {
            uint32_t ah[4], kf[4][4];
            LDMX4(ah, qbase + a_off + kk * 32);
#pragma unroll
            for (int p = 0; p < 4; ++p)
                LDMX4(kf[p], kbase + (uint32_t)(p * 16) * DSTR + b_off + kk * 32);
#pragma unroll
            for (int p = 0; p < 4; ++p) {
                MMAH(sc[2 * p],     ah, kf[p]);
                MMAH(sc[2 * p + 1], ah, kf[p] + 2);
            }
        }

        const int k0 = t * KT;
        const bool tail = (t + 2 >= T);
#pragma unroll
        for (int tl = 0; tl < 8; ++tl)
#pragma unroll
            for (int v = 0; v < 4; ++v) {
                float x = sc[tl][v] * SC;
                if (tail) {
                    int col = k0 + tl * 8 + (lane & 3) * 2 + (v & 1);
                    int row = q0 + wid * 16 + (lane >> 2) + ((v >> 1) << 3);
                    if (col > row) x = -1e30f;
                }
                sc[tl][v] = x;
            }

        // ---- online softmax; pack P to fp16 fragments ----
        uint32_t PH0[8], PH1[8];
#pragma unroll
        for (int hh = 0; hh < 2; ++hh) {
            float rm = -1e30f;
#pragma unroll
            for (int tl = 0; tl < 8; ++tl)
                rm = fmaxf(rm, fmaxf(sc[tl][2 * hh], sc[tl][2 * hh + 1]));
            rm = fmaxf(rm, __shfl_xor_sync(0xffffffffu, rm, 1));
            rm = fmaxf(rm, __shfl_xor_sync(0xffffffffu, rm, 2));
            float mnew = fmaxf(mi[hh], rm);
            float corr = fexp2(mi[hh] - mnew);
            float rs = 0.f;
#pragma unroll
            for (int tl = 0; tl < 8; ++tl) {
                float p0 = fexp2(sc[tl][2 * hh]     - mnew);
                float p1 = fexp2(sc[tl][2 * hh + 1] - mnew);
                rs += p0 + p1;
                __half2 hp = __floats2half2_rn(p0, p1);
                if (hh == 0) PH0[tl] = *(uint32_t*)&hp;
                else         PH1[tl] = *(uint32_t*)&hp;
            }
            rs += __shfl_xor_sync(0xffffffffu, rs, 1);
            rs += __shfl_xor_sync(0xffffffffu, rs, 2);
            li[hh] = li[hh] * corr + rs;
            mi[hh] = mnew;
#pragma unroll
            for (int j = 0; j < 16; ++j) {
                o[j][2 * hh]     *= corr;
                o[j][2 * hh + 1] *= corr;
            }
        }

        // ---- O += P V (P fragments from registers, V via ldmatrix.trans) ----
#pragma unroll
        for (int kk2 = 0; kk2 < 4; ++kk2) {
            uint32_t ph[4] = {PH0[2 * kk2], PH1[2 * kk2], PH0[2 * kk2 + 1], PH1[2 * kk2 + 1]};
#pragma unroll
            for (int half = 0; half < 2; ++half) {
                uint32_t vf[4][4];
#pragma unroll
                for (int p = 0; p < 4; ++p)
                    LDMX4T(vf[p], vbase + (uint32_t)(kk2 * 16) * DSTR + a_off
                                  + (half * 4 + p) * 32);
#pragma unroll
                for (int p = 0; p < 4; ++p) {
                    int q = half * 4 + p;
                    MMAH(o[2 * q],     ph, vf[p]);
                    MMAH(o[2 * q + 1], ph, vf[p] + 2);
                }
            }
        }

        __syncthreads();
        if (t + 2 < T) { KVFILL(s, t + 2); CP_COMMIT(); }
    }

    // ---- epilogue: normalize, sigmoid-gate, fp16 store ----
#pragma unroll
    for (int hh = 0; hh < 2; ++hh) {
        int row = q0 + wid * 16 + (lane >> 2) + hh * 8;
        size_t m = (size_t)b * S_ + row;
        float inv = 1.f / li[hh];
        const float* gr = gate + m * HID + h * D_;
        __half* oa = g_at + m * HID + h * D_;
#pragma unroll
        for (int j = 0; j < 16; ++j) {
            int d0 = j * 8 + (lane & 3) * 2;
            float2 gv = *(const float2*)(gr + d0);
            float s0 = 1.f / (1.f + fexp2(-gv.x * 1.4426950408889634f));
            float s1 = 1.f / (1.f + fexp2(-gv.y * 1.4426950408889634f));
            float v0 = o[j][2 * hh]     * inv * s0;
            float v1 = o[j][2 * hh + 1] * inv * s1;
            *(__half2*)(oa + d0) = __floats2half2_rn(v0, v1);
        }
    }
#undef KVFILL
}

// ---------------- launch ----------------
extern "C" void kernel_launch(void* const* d_in, const int* in_sizes, int n_in,
                              void* d_out, int out_size)
{
    const float* hs   = (const float*)d_in[0];
    const float* cosT = (const float*)d_in[1];
    const float* sinT = (const float*)d_in[2];
    const float* Wq   = (const float*)d_in[3];
    const float* Wk   = (const float*)d_in[4];
    const float* Wv   = (const float*)d_in[5];
    const float* Wg   = (const float*)d_in[6];
    const float* Wo   = (const float*)d_in[7];
    const float* qw   = (const float*)d_in[8];
    const float* kw   = (const float*)d_in[9];
    float* out = (float*)d_out;

    float* gp;
    cudaGetSymbolAddress((void**)&gp, g_gate);

    __half *hsh, *wqh, *wkh, *wvh, *wgh, *woh, *ath;
    cudaGetSymbolAddress((void**)&hsh, g_hs);
    cudaGetSymbolAddress((void**)&wqh, g_wq);
    cudaGetSymbolAddress((void**)&wkh, g_wk);
    cudaGetSymbolAddress((void**)&wvh, g_wv);
    cudaGetSymbolAddress((void**)&wgh, g_wg);
    cudaGetSymbolAddress((void**)&woh, g_wo);
    cudaGetSymbolAddress((void**)&ath, g_at);

    cudaFuncSetAttribute(gemm_qkvg, cudaFuncAttributeMaxDynamicSharedMemorySize, GEMM_SMEM);
    cudaFuncSetAttribute(gemm_f16,  cudaFuncAttributeMaxDynamicSharedMemorySize, GEMM_SMEM);
    cudaFuncSetAttribute(attn_tc,   cudaFuncAttributeMaxDynamicSharedMemorySize, ATTN_SMEM);

    // fp32 -> fp16 converts
    const int nHS = MROWS * HID, nSq = HID * HID, nKv = KVW * HID;
    to_half<<<nHS / 1024, 256>>>(hs, hsh, nHS);
    to_half<<<nSq / 1024, 256>>>(Wq, wqh, nSq);
    to_half<<<nKv / 1024, 256>>>(Wk, wkh, nKv);
    to_half<<<nKv / 1024, 256>>>(Wv, wvh, nKv);
    to_half<<<nSq / 1024, 256>>>(Wg, wgh, nSq);
    to_half<<<nSq / 1024, 256>>>(Wo, woh, nSq);

    // fused Q/K/V/G projections (fp16 tensor cores, BK=64)
    gemm_qkvg<<<dim3(40, MROWS / 128), 128, GEMM_SMEM>>>();

    // RMSNorm + RoPE + transpose -> fp16 q/k/v
    {
        int total_warps = MROWS * (HQ + 2 * HKV);
        rope_norm_kernel<<<total_warps / 8, 256>>>(cosT, sinT, qw, kw);
    }

    // tensor-core causal flash attention + gated epilogue
    attn_tc<<<dim3(S_ / QR, B_ * HQ), 256, ATTN_SMEM>>>(gp);

    // output projection
    gemm_f16<<<dim3(HID / 128, MROWS / 128), 128, GEMM_SMEM>>>(ath, woh, out, HID, HID);
}